// round 2
// baseline (speedup 1.0000x reference)
#include <cuda_runtime.h>
#include <math.h>

#define BB 16
#define CC 256
#define NN 4096
#define HH 8
#define DD 64
#define HID 512
#define THID 1536
#define NSPLIT 8
#define SCALE 0.125f
#define SQRTC 16.0f

// ---------------- scratch (device globals; no runtime allocation) ----------------
__device__ float g_qkv[(size_t)BB * THID * NN];          // 402 MB: q rows [0,512), k [512,1024), v [1024,1536)
__device__ float g_kM[BB * HID];                         // k row max
__device__ float g_kS[BB * HID];                         // k row sum-exp
__device__ float g_ctxp[(size_t)NSPLIT * BB * HH * DD * DD]; // context partials over n-splits
__device__ float g_ctx[(size_t)BB * HH * DD * DD];       // reduced context / S
__device__ float g_At[(size_t)BB * HID * CC];            // A transposed: [b][h*64+d][c]

// ---------------- K1: qkv = w_qkv @ x  (per batch [1536x256]x[256x4096]) ----------------
__global__ __launch_bounds__(256) void k_qkv_gemm(const float* __restrict__ x,
                                                  const float* __restrict__ w) {
    __shared__ float Ws[16][128];   // k-major
    __shared__ float Xs[16][128];
    int t = threadIdx.x;
    int tx = t & 15, ty = t >> 4;
    int b = blockIdx.z;
    int m0 = blockIdx.y * 128;
    int n0 = blockIdx.x * 128;

    const float* wp = w + (size_t)(m0 + (t >> 1)) * CC + (t & 1) * 8;
    const float* xp = x + (size_t)b * CC * NN + (size_t)(t >> 4) * NN + n0 + (t & 15) * 8;

    float acc[8][8];
#pragma unroll
    for (int i = 0; i < 8; i++)
#pragma unroll
        for (int j = 0; j < 8; j++) acc[i][j] = 0.f;

    for (int k0 = 0; k0 < CC; k0 += 16) {
        float4 w0 = *(const float4*)(wp + k0);
        float4 w1 = *(const float4*)(wp + k0 + 4);
        float4 x0 = *(const float4*)(xp + (size_t)k0 * NN);
        float4 x1 = *(const float4*)(xp + (size_t)k0 * NN + 4);
        __syncthreads();
        int mm = t >> 1, kq = (t & 1) * 8;
        Ws[kq + 0][mm] = w0.x; Ws[kq + 1][mm] = w0.y; Ws[kq + 2][mm] = w0.z; Ws[kq + 3][mm] = w0.w;
        Ws[kq + 4][mm] = w1.x; Ws[kq + 5][mm] = w1.y; Ws[kq + 6][mm] = w1.z; Ws[kq + 7][mm] = w1.w;
        *(float4*)&Xs[t >> 4][(t & 15) * 8]     = x0;
        *(float4*)&Xs[t >> 4][(t & 15) * 8 + 4] = x1;
        __syncthreads();
#pragma unroll
        for (int kk = 0; kk < 16; kk++) {
            float a[8], bb[8];
            *(float4*)&a[0]  = *(float4*)&Ws[kk][ty * 8];
            *(float4*)&a[4]  = *(float4*)&Ws[kk][ty * 8 + 4];
            *(float4*)&bb[0] = *(float4*)&Xs[kk][tx * 8];
            *(float4*)&bb[4] = *(float4*)&Xs[kk][tx * 8 + 4];
#pragma unroll
            for (int i = 0; i < 8; i++)
#pragma unroll
                for (int j = 0; j < 8; j++) acc[i][j] = fmaf(a[i], bb[j], acc[i][j]);
        }
    }
    float* op = g_qkv + ((size_t)b * THID + m0 + ty * 8) * NN + n0 + tx * 8;
#pragma unroll
    for (int i = 0; i < 8; i++) {
        *(float4*)(op + (size_t)i * NN)     = make_float4(acc[i][0], acc[i][1], acc[i][2], acc[i][3]);
        *(float4*)(op + (size_t)i * NN + 4) = make_float4(acc[i][4], acc[i][5], acc[i][6], acc[i][7]);
    }
}

// ---------------- K2: k row stats (max, sum-exp over n=4096) ----------------
__global__ __launch_bounds__(256) void k_kstats() {
    int row = blockIdx.x;             // 0 .. B*HID-1
    int b = row >> 9, r = row & 511;
    const float4* p = (const float4*)(g_qkv + ((size_t)b * THID + HID + r) * NN);
    int t = threadIdx.x;
    float4 v[4];
    float m = -1e30f;
#pragma unroll
    for (int i = 0; i < 4; i++) {
        v[i] = p[t + i * 256];
        m = fmaxf(m, fmaxf(fmaxf(v[i].x, v[i].y), fmaxf(v[i].z, v[i].w)));
    }
    __shared__ float sred[8];
#pragma unroll
    for (int o = 16; o > 0; o >>= 1) m = fmaxf(m, __shfl_xor_sync(0xffffffffu, m, o));
    if ((t & 31) == 0) sred[t >> 5] = m;
    __syncthreads();
    float M = sred[0];
#pragma unroll
    for (int w = 1; w < 8; w++) M = fmaxf(M, sred[w]);
    __syncthreads();
    float s = 0.f;
#pragma unroll
    for (int i = 0; i < 4; i++)
        s += __expf(v[i].x - M) + __expf(v[i].y - M) + __expf(v[i].z - M) + __expf(v[i].w - M);
#pragma unroll
    for (int o = 16; o > 0; o >>= 1) s += __shfl_xor_sync(0xffffffffu, s, o);
    if ((t & 31) == 0) sred[t >> 5] = s;
    __syncthreads();
    if (t == 0) {
        float S = 0.f;
#pragma unroll
        for (int w = 0; w < 8; w++) S += sred[w];
        g_kM[row] = M;
        g_kS[row] = S;
    }
}

// ---------------- K3: context partials: ctxp[sp] = exp(k - M) @ v^T over n-range ----------------
__global__ __launch_bounds__(256) void k_context() {
    __shared__ float ksT[64][68];    // [n][d], padded for conflict-free transposed access
    __shared__ float vsT[64][68];
    __shared__ float Ms[64];
    int t = threadIdx.x;
    int sp = blockIdx.x, h = blockIdx.y, b = blockIdx.z;
    if (t < 64) Ms[t] = g_kM[b * HID + h * 64 + t];
    const float* kg = g_qkv + ((size_t)b * THID + HID + h * 64) * NN;
    const float* vg = g_qkv + ((size_t)b * THID + 2 * HID + h * 64) * NN;
    int tx = t & 15, ty = t >> 4;
    float acc[4][4];
#pragma unroll
    for (int i = 0; i < 4; i++)
#pragma unroll
        for (int j = 0; j < 4; j++) acc[i][j] = 0.f;

    for (int c0 = sp * 512; c0 < sp * 512 + 512; c0 += 64) {
        __syncthreads();
#pragma unroll
        for (int i = 0; i < 4; i++) {
            int lin = t + i * 256;
            int d = lin >> 4, n4 = lin & 15;
            float4 kf = *(const float4*)(kg + (size_t)d * NN + c0 + n4 * 4);
            float mM = Ms[d];
            ksT[n4 * 4 + 0][d] = __expf(kf.x - mM);
            ksT[n4 * 4 + 1][d] = __expf(kf.y - mM);
            ksT[n4 * 4 + 2][d] = __expf(kf.z - mM);
            ksT[n4 * 4 + 3][d] = __expf(kf.w - mM);
            float4 vf = *(const float4*)(vg + (size_t)d * NN + c0 + n4 * 4);
            vsT[n4 * 4 + 0][d] = vf.x;
            vsT[n4 * 4 + 1][d] = vf.y;
            vsT[n4 * 4 + 2][d] = vf.z;
            vsT[n4 * 4 + 3][d] = vf.w;
        }
        __syncthreads();
#pragma unroll
        for (int n = 0; n < 64; n++) {
            float a[4], bb[4];
            *(float4*)a  = *(float4*)&ksT[n][ty * 4];
            *(float4*)bb = *(float4*)&vsT[n][tx * 4];
#pragma unroll
            for (int i = 0; i < 4; i++)
#pragma unroll
                for (int j = 0; j < 4; j++) acc[i][j] = fmaf(a[i], bb[j], acc[i][j]);
        }
    }
    float* op = g_ctxp + (((size_t)sp * BB + b) * HH + h) * DD * DD + (ty * 4) * DD + tx * 4;
#pragma unroll
    for (int i = 0; i < 4; i++)
        *(float4*)(op + i * DD) = make_float4(acc[i][0], acc[i][1], acc[i][2], acc[i][3]);
}

// ---------------- K4a: reduce partials, divide by softmax denom ----------------
__global__ __launch_bounds__(256) void k_ctxred() {
    int idx = blockIdx.x * 256 + threadIdx.x;     // < B*H*D*D = 524288
    float s = 0.f;
#pragma unroll
    for (int p = 0; p < NSPLIT; p++) s += g_ctxp[(size_t)p * (BB * HH * DD * DD) + idx];
    int d = (idx >> 6) & 63;
    int h = (idx >> 12) & 7;
    int b = idx >> 15;
    g_ctx[idx] = s / g_kS[b * HID + h * 64 + d];
}

// ---------------- K4b: A^T[b][h*64+d][c] = sum_e Wout[c][h*64+e] * ctx[b][h][d][e] ----------------
__global__ __launch_bounds__(128) void k_Agemm(const float* __restrict__ wout) {
    __shared__ float Wouts[128][64];
    __shared__ float ctxs[64][64];
    int t = threadIdx.x;
    int cseg = blockIdx.x, h = blockIdx.y, b = blockIdx.z;
    int cbase = cseg * 128;
#pragma unroll
    for (int i = 0; i < 16; i++) {
        int lin4 = t + i * 128;                  // 2048 float4
        int c = lin4 >> 4, e4 = lin4 & 15;
        *(float4*)&Wouts[c][e4 * 4] = *(const float4*)(wout + (size_t)(cbase + c) * HID + h * 64 + e4 * 4);
    }
    const float* ctxg = g_ctx + ((size_t)b * HH + h) * DD * DD;
#pragma unroll
    for (int i = 0; i < 8; i++) {
        int lin4 = t + i * 128;                  // 1024 float4
        int d = lin4 >> 4, e4 = lin4 & 15;
        *(float4*)&ctxs[d][e4 * 4] = *(const float4*)(ctxg + d * 64 + e4 * 4);
    }
    __syncthreads();
    float acc[64];
#pragma unroll
    for (int d = 0; d < 64; d++) acc[d] = 0.f;
    for (int e = 0; e < 64; e++) {
        float w = Wouts[t][e];
#pragma unroll
        for (int d = 0; d < 64; d++) acc[d] = fmaf(w, ctxs[d][e], acc[d]);
    }
    float* op = g_At + ((size_t)b * HID + h * 64) * CC + cbase + t;
    for (int d = 0; d < 64; d++) op[(size_t)d * CC] = acc[d];
}

// ---------------- K5: y = RMSNorm( A_b @ softmax_d(q)*SCALE + b_out ) ----------------
__global__ __launch_bounds__(256) void k_final(const float* __restrict__ bo,
                                               const float* __restrict__ g,
                                               float* __restrict__ y) {
    __shared__ float qh[64][64];    // per-head q tile [d][n]
    __shared__ float As[16][256];   // A chunk [dd][c]
    __shared__ float redM[4][64];
    __shared__ float redS[4][64];
    __shared__ float colM[64];
    __shared__ float colS[64];
    __shared__ float rss[16][16][4];
    int t = threadIdx.x;
    int b = blockIdx.y, n0 = blockIdx.x * 64;
    int cg = t >> 4, ng = t & 15;
    int part = t >> 6, col = t & 63;

    float acc[16][4];
#pragma unroll
    for (int ci = 0; ci < 16; ci++)
#pragma unroll
        for (int j = 0; j < 4; j++) acc[ci][j] = 0.f;

    for (int h = 0; h < 8; h++) {
        __syncthreads();
#pragma unroll
        for (int i = 0; i < 4; i++) {
            int lin4 = t + i * 256;
            int d = lin4 >> 4, n4 = lin4 & 15;
            *(float4*)&qh[d][n4 * 4] =
                *(const float4*)(g_qkv + ((size_t)b * THID + h * 64 + d) * NN + n0 + n4 * 4);
        }
        __syncthreads();
        // softmax over d (64 rows) per column; 4 threads per column
        float lm = -1e30f;
#pragma unroll
        for (int r = 0; r < 16; r++) lm = fmaxf(lm, qh[part * 16 + r][col]);
        redM[part][col] = lm;
        __syncthreads();
        float M = fmaxf(fmaxf(redM[0][col], redM[1][col]), fmaxf(redM[2][col], redM[3][col]));
        float ls = 0.f;
#pragma unroll
        for (int r = 0; r < 16; r++) ls += __expf(qh[part * 16 + r][col] - M);
        redS[part][col] = ls;
        __syncthreads();
        if (t < 64) {
            colM[t] = M;   // part==0 threads: col == t, M is that column's max
            float S = redS[0][t] + redS[1][t] + redS[2][t] + redS[3][t];
            colS[t] = SCALE / S;
        }
        __syncthreads();
#pragma unroll
        for (int i = 0; i < 16; i++) {
            int lin = t + i * 256;
            int d = lin >> 6, n = lin & 63;
            qh[d][n] = __expf(qh[d][n] - colM[n]) * colS[n];
        }
        // y_tile += A_h @ qh  (K=64 in 4 chunks of 16, A staged via smem)
        for (int dc = 0; dc < 4; dc++) {
            __syncthreads();
#pragma unroll
            for (int i = 0; i < 4; i++) {
                int lin4 = t + i * 256;
                int dd = lin4 >> 6, c4 = lin4 & 63;
                *(float4*)&As[dd][c4 * 4] =
                    *(const float4*)(g_At + ((size_t)b * HID + h * 64 + dc * 16 + dd) * CC + c4 * 4);
            }
            __syncthreads();
#pragma unroll
            for (int dd = 0; dd < 16; dd++) {
                float qv[4];
                *(float4*)qv = *(float4*)&qh[dc * 16 + dd][ng * 4];
                float a[16];
                *(float4*)&a[0]  = *(float4*)&As[dd][cg * 16];
                *(float4*)&a[4]  = *(float4*)&As[dd][cg * 16 + 4];
                *(float4*)&a[8]  = *(float4*)&As[dd][cg * 16 + 8];
                *(float4*)&a[12] = *(float4*)&As[dd][cg * 16 + 12];
#pragma unroll
                for (int ci = 0; ci < 16; ci++)
#pragma unroll
                    for (int j = 0; j < 4; j++)
                        acc[ci][j] = fmaf(a[ci], qv[j], acc[ci][j]);
            }
        }
    }
    // bias + RMSNorm over channel dim
    float ssq[4] = {0.f, 0.f, 0.f, 0.f};
#pragma unroll
    for (int ci = 0; ci < 16; ci++) {
        float bb = bo[cg * 16 + ci];
#pragma unroll
        for (int j = 0; j < 4; j++) {
            acc[ci][j] += bb;
            ssq[j] += acc[ci][j] * acc[ci][j];
        }
    }
#pragma unroll
    for (int j = 0; j < 4; j++) rss[cg][ng][j] = ssq[j];
    __syncthreads();
    float sc[4];
#pragma unroll
    for (int j = 0; j < 4; j++) {
        float tot = 0.f;
#pragma unroll
        for (int k = 0; k < 16; k++) tot += rss[k][ng][j];
        float nr = sqrtf(tot);
        sc[j] = SQRTC / fmaxf(nr, 1e-12f);
    }
#pragma unroll
    for (int ci = 0; ci < 16; ci++) {
        int c = cg * 16 + ci;
        float gc = g[c];
        float4 o;
        o.x = acc[ci][0] * sc[0] * gc;
        o.y = acc[ci][1] * sc[1] * gc;
        o.z = acc[ci][2] * sc[2] * gc;
        o.w = acc[ci][3] * sc[3] * gc;
        *(float4*)(y + ((size_t)b * CC + c) * NN + n0 + ng * 4) = o;
    }
}

// ---------------- launch ----------------
extern "C" void kernel_launch(void* const* d_in, const int* in_sizes, int n_in,
                              void* d_out, int out_size) {
    const float* x      = (const float*)d_in[0];
    const float* w_qkv  = (const float*)d_in[1];
    const float* w_out  = (const float*)d_in[2];
    const float* b_out  = (const float*)d_in[3];
    const float* g_norm = (const float*)d_in[4];
    float* y = (float*)d_out;

    k_qkv_gemm<<<dim3(32, 12, 16), 256>>>(x, w_qkv);
    k_kstats<<<BB * HID, 256>>>();
    k_context<<<dim3(NSPLIT, HH, BB), 256>>>();
    k_ctxred<<<(BB * HH * DD * DD) / 256, 256>>>();
    k_Agemm<<<dim3(2, HH, BB), 128>>>(w_out);
    k_final<<<dim3(NN / 64, BB), 256>>>(b_out, g_norm, y);
}

// round 3
// speedup vs baseline: 2.4947x; 2.4947x over previous
#include <cuda_runtime.h>
#include <math.h>
#include <stdint.h>

#define BB 16
#define CC 256
#define NN 4096
#define HH 8
#define DD 64
#define HID 512
#define THID 1536
#define NSPLIT 8
#define SCALE 0.125f
#define SQRTC 16.0f

// ---------------- scratch (device globals; no runtime allocation) ----------------
__device__ float g_qkv[(size_t)BB * THID * NN];          // q rows [0,512) (later overwritten by softmaxed q), k, v
__device__ float g_wt[(size_t)CC * THID];                // w_qkv transposed: [k=256][m=1536]
__device__ float g_kM[BB * HID];
__device__ float g_kS[BB * HID];
__device__ float g_ctxp[(size_t)NSPLIT * BB * HH * DD * DD];
__device__ float g_ctx[(size_t)BB * HH * DD * DD];
__device__ float g_At[(size_t)BB * HID * CC];            // A^T: [b][hd=512][c=256]
__device__ float g_ssqp[(size_t)2 * BB * NN];            // per-mblock ssq partials

// ---------------- helpers ----------------
__device__ __forceinline__ uint32_t f2tf32(float x) {
    uint32_t u;
    asm("cvt.rna.tf32.f32 %0, %1;" : "=r"(u) : "f"(x));
    return u;
}
#define CP16(sm, gp) asm volatile("cp.async.cg.shared.global [%0], [%1], 16;" :: "r"(sm), "l"(gp))
#define CP_COMMIT() asm volatile("cp.async.commit_group;")
#define CP_WAIT1() asm volatile("cp.async.wait_group 1;")
#define CP_WAIT0() asm volatile("cp.async.wait_group 0;")

__device__ __forceinline__ void mma_tf32(float* c, const uint32_t* a, const uint32_t* b) {
    asm volatile(
        "mma.sync.aligned.m16n8k8.row.col.f32.tf32.tf32.f32 "
        "{%0,%1,%2,%3}, {%4,%5,%6,%7}, {%8,%9}, {%0,%1,%2,%3};"
        : "+f"(c[0]), "+f"(c[1]), "+f"(c[2]), "+f"(c[3])
        : "r"(a[0]), "r"(a[1]), "r"(a[2]), "r"(a[3]), "r"(b[0]), "r"(b[1]));
}

// ---------------- K0: transpose w_qkv [1536x256] -> g_wt [256x1536] ----------------
__global__ __launch_bounds__(256) void k_wt(const float* __restrict__ w) {
    __shared__ float tl[32][33];
    int k0 = blockIdx.x * 32, m0 = blockIdx.y * 32;
    int tx = threadIdx.x, ty = threadIdx.y;  // 32 x 8
#pragma unroll
    for (int i = 0; i < 4; i++)
        tl[ty + i * 8][tx] = w[(size_t)(m0 + ty + i * 8) * CC + k0 + tx];
    __syncthreads();
#pragma unroll
    for (int i = 0; i < 4; i++)
        g_wt[(size_t)(k0 + ty + i * 8) * THID + m0 + tx] = tl[tx][ty + i * 8];
}

// ---------------- tf32 GEMM template: C[M x NN] = A[K x M]^T-view @ B[K x NN] ----------------
// MODE 0: A=g_wt (shared),   B=x + b*CC*NN,   C=g_qkv + b*THID*NN   (plain store)
// MODE 1: A=g_At + b*HID*CC, B=qs (g_qkv q rows), C=y + b*CC*NN     (bias + ssq partials)
template <int MDIM, int KDIM, int MODE>
__global__ __launch_bounds__(256) void gemm_tf32(const float* __restrict__ Bsrc,
                                                 float* __restrict__ Cdst,
                                                 const float* __restrict__ bias) {
    __shared__ float As[2][16][136];
    __shared__ float Bs[2][16][136];
    __shared__ float s_red[128][2];

    const int t = threadIdx.x;
    const int b = blockIdx.z;
    const int m0 = blockIdx.y * 128;
    const int n0 = blockIdx.x * 128;

    const float* Ab = (MODE == 0) ? g_wt : (g_At + (size_t)b * HID * CC);
    const float* Bb = (MODE == 0) ? (Bsrc + (size_t)b * CC * NN)
                                  : (g_qkv + (size_t)b * THID * NN);
    float* Cb = Cdst + (size_t)b * (MODE == 0 ? THID : CC) * NN;

    // copy-thread mapping: 512 16B chunks per operand per stage, 2 per thread
    const int id0 = t, id1 = t + 256;
    const int ar0 = id0 >> 5, ac0 = (id0 & 31) * 4;
    const int ar1 = id1 >> 5, ac1 = (id1 & 31) * 4;
    unsigned sA0[2], sA1[2], sB0[2], sB1[2];
#pragma unroll
    for (int s = 0; s < 2; s++) {
        sA0[s] = (unsigned)__cvta_generic_to_shared(&As[s][ar0][ac0]);
        sA1[s] = (unsigned)__cvta_generic_to_shared(&As[s][ar1][ac1]);
        sB0[s] = (unsigned)__cvta_generic_to_shared(&Bs[s][ar0][ac0]);
        sB1[s] = (unsigned)__cvta_generic_to_shared(&Bs[s][ar1][ac1]);
    }

    const int wid = t >> 5, lane = t & 31;
    const int wm = (wid >> 2) * 64;     // warp m offset (2 warps in m)
    const int wn = (wid & 3) * 32;      // warp n offset (4 warps in n)
    const int g = lane >> 2, t4 = lane & 3;

    float acc[4][4][4];
#pragma unroll
    for (int mt = 0; mt < 4; mt++)
#pragma unroll
        for (int nt = 0; nt < 4; nt++)
#pragma unroll
            for (int r = 0; r < 4; r++) acc[mt][nt][r] = 0.f;

    const int NK = KDIM / 16;
    // prologue: stage 0
    {
        CP16(sA0[0], Ab + (size_t)ar0 * MDIM + m0 + ac0);
        CP16(sA1[0], Ab + (size_t)ar1 * MDIM + m0 + ac1);
        CP16(sB0[0], Bb + (size_t)ar0 * NN + n0 + ac0);
        CP16(sB1[0], Bb + (size_t)ar1 * NN + n0 + ac1);
        CP_COMMIT();
    }
    for (int kt = 0; kt < NK; kt++) {
        if (kt + 1 < NK) {
            const int k0 = (kt + 1) * 16;
            const int buf = (kt + 1) & 1;
            CP16(sA0[buf], Ab + (size_t)(k0 + ar0) * MDIM + m0 + ac0);
            CP16(sA1[buf], Ab + (size_t)(k0 + ar1) * MDIM + m0 + ac1);
            CP16(sB0[buf], Bb + (size_t)(k0 + ar0) * NN + n0 + ac0);
            CP16(sB1[buf], Bb + (size_t)(k0 + ar1) * NN + n0 + ac1);
            CP_COMMIT();
            CP_WAIT1();
        } else {
            CP_WAIT0();
        }
        __syncthreads();
        const int buf = kt & 1;
#pragma unroll
        for (int kk = 0; kk < 16; kk += 8) {
            uint32_t a[4][4], bf[4][2];
#pragma unroll
            for (int mt = 0; mt < 4; mt++) {
                int mr = wm + mt * 16 + g;
                a[mt][0] = f2tf32(As[buf][kk + t4][mr]);
                a[mt][1] = f2tf32(As[buf][kk + t4][mr + 8]);
                a[mt][2] = f2tf32(As[buf][kk + t4 + 4][mr]);
                a[mt][3] = f2tf32(As[buf][kk + t4 + 4][mr + 8]);
            }
#pragma unroll
            for (int nt = 0; nt < 4; nt++) {
                int nc = wn + nt * 8 + g;
                bf[nt][0] = f2tf32(Bs[buf][kk + t4][nc]);
                bf[nt][1] = f2tf32(Bs[buf][kk + t4 + 4][nc]);
            }
#pragma unroll
            for (int mt = 0; mt < 4; mt++)
#pragma unroll
                for (int nt = 0; nt < 4; nt++) mma_tf32(acc[mt][nt], a[mt], bf[nt]);
        }
        __syncthreads();
    }

    // ---------------- epilogue ----------------
    if (MODE == 0) {
#pragma unroll
        for (int mt = 0; mt < 4; mt++) {
            int row = m0 + wm + mt * 16 + g;
#pragma unroll
            for (int nt = 0; nt < 4; nt++) {
                int col = n0 + wn + nt * 8 + 2 * t4;
                *(float2*)(Cb + (size_t)row * NN + col) =
                    make_float2(acc[mt][nt][0], acc[mt][nt][1]);
                *(float2*)(Cb + (size_t)(row + 8) * NN + col) =
                    make_float2(acc[mt][nt][2], acc[mt][nt][3]);
            }
        }
    } else {
        float ps[4][2];
#pragma unroll
        for (int nt = 0; nt < 4; nt++) { ps[nt][0] = 0.f; ps[nt][1] = 0.f; }
#pragma unroll
        for (int mt = 0; mt < 4; mt++) {
            int row = m0 + wm + mt * 16 + g;
            float b0v = bias[row], b1v = bias[row + 8];
#pragma unroll
            for (int nt = 0; nt < 4; nt++) {
                int col = n0 + wn + nt * 8 + 2 * t4;
                float v0 = acc[mt][nt][0] + b0v;
                float v1 = acc[mt][nt][1] + b0v;
                float v2 = acc[mt][nt][2] + b1v;
                float v3 = acc[mt][nt][3] + b1v;
                *(float2*)(Cb + (size_t)row * NN + col) = make_float2(v0, v1);
                *(float2*)(Cb + (size_t)(row + 8) * NN + col) = make_float2(v2, v3);
                ps[nt][0] += v0 * v0 + v2 * v2;
                ps[nt][1] += v1 * v1 + v3 * v3;
            }
        }
        // reduce over g (lanes differing in bits 2..4)
#pragma unroll
        for (int nt = 0; nt < 4; nt++)
#pragma unroll
            for (int j = 0; j < 2; j++) {
#pragma unroll
                for (int o = 4; o <= 16; o <<= 1)
                    ps[nt][j] += __shfl_xor_sync(0xffffffffu, ps[nt][j], o);
            }
        if (g == 0) {
            int wmi = wid >> 2;
#pragma unroll
            for (int nt = 0; nt < 4; nt++) {
#pragma unroll
                for (int j = 0; j < 2; j++)
                    s_red[wn + nt * 8 + 2 * t4 + j][wmi] = ps[nt][j];
            }
        }
        __syncthreads();
        if (t < 128)
            g_ssqp[(size_t)blockIdx.y * BB * NN + (size_t)b * NN + n0 + t] =
                s_red[t][0] + s_red[t][1];
    }
}

// ---------------- K2: k row stats ----------------
__global__ __launch_bounds__(256) void k_kstats() {
    int row = blockIdx.x;
    int b = row >> 9, r = row & 511;
    const float4* p = (const float4*)(g_qkv + ((size_t)b * THID + HID + r) * NN);
    int t = threadIdx.x;
    float4 v[4];
    float m = -1e30f;
#pragma unroll
    for (int i = 0; i < 4; i++) {
        v[i] = p[t + i * 256];
        m = fmaxf(m, fmaxf(fmaxf(v[i].x, v[i].y), fmaxf(v[i].z, v[i].w)));
    }
    __shared__ float sred[8];
#pragma unroll
    for (int o = 16; o > 0; o >>= 1) m = fmaxf(m, __shfl_xor_sync(0xffffffffu, m, o));
    if ((t & 31) == 0) sred[t >> 5] = m;
    __syncthreads();
    float M = sred[0];
#pragma unroll
    for (int w = 1; w < 8; w++) M = fmaxf(M, sred[w]);
    __syncthreads();
    float s = 0.f;
#pragma unroll
    for (int i = 0; i < 4; i++)
        s += __expf(v[i].x - M) + __expf(v[i].y - M) + __expf(v[i].z - M) + __expf(v[i].w - M);
#pragma unroll
    for (int o = 16; o > 0; o >>= 1) s += __shfl_xor_sync(0xffffffffu, s, o);
    if ((t & 31) == 0) sred[t >> 5] = s;
    __syncthreads();
    if (t == 0) {
        float S = 0.f;
#pragma unroll
        for (int w = 0; w < 8; w++) S += sred[w];
        g_kM[row] = M;
        g_kS[row] = S;
    }
}

// ---------------- K3: context partials ----------------
__global__ __launch_bounds__(256) void k_context() {
    __shared__ float ksT[64][68];
    __shared__ float vsT[64][68];
    __shared__ float Ms[64];
    int t = threadIdx.x;
    int sp = blockIdx.x, h = blockIdx.y, b = blockIdx.z;
    if (t < 64) Ms[t] = g_kM[b * HID + h * 64 + t];
    const float* kg = g_qkv + ((size_t)b * THID + HID + h * 64) * NN;
    const float* vg = g_qkv + ((size_t)b * THID + 2 * HID + h * 64) * NN;
    int tx = t & 15, ty = t >> 4;
    float acc[4][4];
#pragma unroll
    for (int i = 0; i < 4; i++)
#pragma unroll
        for (int j = 0; j < 4; j++) acc[i][j] = 0.f;

    for (int c0 = sp * 512; c0 < sp * 512 + 512; c0 += 64) {
        __syncthreads();
#pragma unroll
        for (int i = 0; i < 4; i++) {
            int lin = t + i * 256;
            int d = lin >> 4, n4 = lin & 15;
            float4 kf = *(const float4*)(kg + (size_t)d * NN + c0 + n4 * 4);
            float mM = Ms[d];
            ksT[n4 * 4 + 0][d] = __expf(kf.x - mM);
            ksT[n4 * 4 + 1][d] = __expf(kf.y - mM);
            ksT[n4 * 4 + 2][d] = __expf(kf.z - mM);
            ksT[n4 * 4 + 3][d] = __expf(kf.w - mM);
            float4 vf = *(const float4*)(vg + (size_t)d * NN + c0 + n4 * 4);
            vsT[n4 * 4 + 0][d] = vf.x;
            vsT[n4 * 4 + 1][d] = vf.y;
            vsT[n4 * 4 + 2][d] = vf.z;
            vsT[n4 * 4 + 3][d] = vf.w;
        }
        __syncthreads();
#pragma unroll
        for (int n = 0; n < 64; n++) {
            float a[4], bb[4];
            *(float4*)a  = *(float4*)&ksT[n][ty * 4];
            *(float4*)bb = *(float4*)&vsT[n][tx * 4];
#pragma unroll
            for (int i = 0; i < 4; i++)
#pragma unroll
                for (int j = 0; j < 4; j++) acc[i][j] = fmaf(a[i], bb[j], acc[i][j]);
        }
    }
    float* op = g_ctxp + (((size_t)sp * BB + b) * HH + h) * DD * DD + (ty * 4) * DD + tx * 4;
#pragma unroll
    for (int i = 0; i < 4; i++)
        *(float4*)(op + i * DD) = make_float4(acc[i][0], acc[i][1], acc[i][2], acc[i][3]);
}

// ---------------- K4a: reduce partials ----------------
__global__ __launch_bounds__(256) void k_ctxred() {
    int idx = blockIdx.x * 256 + threadIdx.x;
    float s = 0.f;
#pragma unroll
    for (int p = 0; p < NSPLIT; p++) s += g_ctxp[(size_t)p * (BB * HH * DD * DD) + idx];
    int d = (idx >> 6) & 63;
    int h = (idx >> 12) & 7;
    int b = idx >> 15;
    g_ctx[idx] = s / g_kS[b * HID + h * 64 + d];
}

// ---------------- K4b: A^T[b][hd][c] ----------------
__global__ __launch_bounds__(128) void k_Agemm(const float* __restrict__ wout) {
    __shared__ float Wouts[128][64];
    __shared__ float ctxs[64][64];
    int t = threadIdx.x;
    int cseg = blockIdx.x, h = blockIdx.y, b = blockIdx.z;
    int cbase = cseg * 128;
#pragma unroll
    for (int i = 0; i < 16; i++) {
        int lin4 = t + i * 128;
        int c = lin4 >> 4, e4 = lin4 & 15;
        *(float4*)&Wouts[c][e4 * 4] = *(const float4*)(wout + (size_t)(cbase + c) * HID + h * 64 + e4 * 4);
    }
    const float* ctxg = g_ctx + ((size_t)b * HH + h) * DD * DD;
#pragma unroll
    for (int i = 0; i < 8; i++) {
        int lin4 = t + i * 128;
        int d = lin4 >> 4, e4 = lin4 & 15;
        *(float4*)&ctxs[d][e4 * 4] = *(const float4*)(ctxg + d * 64 + e4 * 4);
    }
    __syncthreads();
    float acc[64];
#pragma unroll
    for (int d = 0; d < 64; d++) acc[d] = 0.f;
    for (int e = 0; e < 64; e++) {
        float w = Wouts[t][e];
#pragma unroll
        for (int d = 0; d < 64; d++) acc[d] = fmaf(w, ctxs[d][e], acc[d]);
    }
    float* op = g_At + ((size_t)b * HID + h * 64) * CC + cbase + t;
    for (int d = 0; d < 64; d++) op[(size_t)d * CC] = acc[d];
}

// ---------------- K_qsoft: in-place softmax over d for q, * SCALE ----------------
__global__ __launch_bounds__(256) void k_qsoft() {
    int t = threadIdx.x;
    int n = blockIdx.x * 256 + t;
    int h = blockIdx.y, b = blockIdx.z;
    float* p = g_qkv + ((size_t)b * THID + h * 64) * NN + n;
    float v[64];
    float m = -1e30f;
#pragma unroll
    for (int d = 0; d < 64; d++) {
        v[d] = p[(size_t)d * NN];
        m = fmaxf(m, v[d]);
    }
    float s = 0.f;
#pragma unroll
    for (int d = 0; d < 64; d++) {
        v[d] = __expf(v[d] - m);
        s += v[d];
    }
    float r = SCALE / s;
#pragma unroll
    for (int d = 0; d < 64; d++) p[(size_t)d * NN] = v[d] * r;
}

// ---------------- K_norm: RMSNorm in place on y ----------------
__global__ __launch_bounds__(256) void k_norm(float* __restrict__ y,
                                              const float* __restrict__ gn) {
    size_t idx = (size_t)blockIdx.x * 256 + threadIdx.x;   // float4 units
    int n4 = (int)(idx % (NN / 4));
    size_t tmp = idx / (NN / 4);
    int c = (int)(tmp % CC);
    int b = (int)(tmp / CC);
    float4 vv = ((float4*)y)[idx];
    const float4 s0 = *(const float4*)(g_ssqp + (size_t)b * NN + n4 * 4);
    const float4 s1 = *(const float4*)(g_ssqp + (size_t)BB * NN + (size_t)b * NN + n4 * 4);
    float gc = gn[c] * SQRTC;
    vv.x *= gc / fmaxf(sqrtf(s0.x + s1.x), 1e-12f);
    vv.y *= gc / fmaxf(sqrtf(s0.y + s1.y), 1e-12f);
    vv.z *= gc / fmaxf(sqrtf(s0.z + s1.z), 1e-12f);
    vv.w *= gc / fmaxf(sqrtf(s0.w + s1.w), 1e-12f);
    ((float4*)y)[idx] = vv;
}

// ---------------- launch ----------------
extern "C" void kernel_launch(void* const* d_in, const int* in_sizes, int n_in,
                              void* d_out, int out_size) {
    const float* x      = (const float*)d_in[0];
    const float* w_qkv  = (const float*)d_in[1];
    const float* w_out  = (const float*)d_in[2];
    const float* b_out  = (const float*)d_in[3];
    const float* g_norm = (const float*)d_in[4];
    float* y = (float*)d_out;

    k_wt<<<dim3(CC / 32, THID / 32), dim3(32, 8)>>>(w_qkv);
    // qkv = w_qkv @ x  (tensor cores, tf32)
    float* qkv_ptr = nullptr;
    cudaGetSymbolAddress((void**)&qkv_ptr, g_qkv);
    gemm_tf32<THID, CC, 0><<<dim3(NN / 128, THID / 128, BB), 256>>>(x, qkv_ptr, nullptr);
    k_kstats<<<BB * HID, 256>>>();
    k_context<<<dim3(NSPLIT, HH, BB), 256>>>();
    k_ctxred<<<(BB * HH * DD * DD) / 256, 256>>>();
    k_Agemm<<<dim3(2, HH, BB), 128>>>(w_out);
    k_qsoft<<<dim3(NN / 256, HH, BB), 256>>>();
    // y_raw = A_b @ qs (tensor cores, tf32) with bias + ssq partials
    gemm_tf32<CC, HID, 1><<<dim3(NN / 128, CC / 128, BB), 256>>>(nullptr, y, b_out);
    k_norm<<<(size_t)BB * CC * NN / 4 / 256, 256>>>(y, g_norm);
}

// round 6
// speedup vs baseline: 2.9406x; 1.1787x over previous
#include <cuda_runtime.h>
#include <math.h>
#include <stdint.h>

#define BB 16
#define CC 256
#define NN 4096
#define HH 8
#define DD 64
#define HID 512
#define THID 1536
#define NSPLIT 8
#define SCALE 0.125f
#define SQRTC 16.0f

// ---------------- scratch ----------------
__device__ float g_qkv[(size_t)BB * THID * NN];   // q [0,512), k [512,1024), v [1024,1536)
__device__ float g_wt[(size_t)CC * THID];         // w_qkv^T [k=256][m=1536]
__device__ float g_ctxp[(size_t)NSPLIT * BB * HH * DD * DD];
__device__ float g_sump[(size_t)NSPLIT * BB * HID];
__device__ float g_ctx[(size_t)BB * HH * DD * DD];
__device__ float g_At[(size_t)BB * HID * CC];     // A^T: [b][hd=512][c=256]

// ---------------- helpers ----------------
__device__ __forceinline__ uint32_t f2tf32(float x) {
    uint32_t u;
    asm("cvt.rna.tf32.f32 %0, %1;" : "=r"(u) : "f"(x));
    return u;
}
#define CP16(sm, gp) asm volatile("cp.async.cg.shared.global [%0], [%1], 16;" :: "r"(sm), "l"(gp))
#define CP_COMMIT() asm volatile("cp.async.commit_group;")
#define CP_WAIT1() asm volatile("cp.async.wait_group 1;")
#define CP_WAIT0() asm volatile("cp.async.wait_group 0;")

__device__ __forceinline__ void mma_tf32(float* c, const uint32_t* a, const uint32_t* b) {
    asm volatile(
        "mma.sync.aligned.m16n8k8.row.col.f32.tf32.tf32.f32 "
        "{%0,%1,%2,%3}, {%4,%5,%6,%7}, {%8,%9}, {%0,%1,%2,%3};"
        : "+f"(c[0]), "+f"(c[1]), "+f"(c[2]), "+f"(c[3])
        : "r"(a[0]), "r"(a[1]), "r"(a[2]), "r"(a[3]), "r"(b[0]), "r"(b[1]));
}

// ---------------- K0: transpose w_qkv [1536x256] -> g_wt [256x1536] ----------------
__global__ __launch_bounds__(256) void k_wt(const float* __restrict__ w) {
    __shared__ float tl[32][33];
    int k0 = blockIdx.x * 32, m0 = blockIdx.y * 32;
    int tx = threadIdx.x, ty = threadIdx.y;
#pragma unroll
    for (int i = 0; i < 4; i++)
        tl[ty + i * 8][tx] = w[(size_t)(m0 + ty + i * 8) * CC + k0 + tx];
    __syncthreads();
#pragma unroll
    for (int i = 0; i < 4; i++)
        g_wt[(size_t)(k0 + ty + i * 8) * THID + m0 + tx] = tl[tx][ty + i * 8];
}

// ---------------- K1: qkv = w_qkv @ x (tf32 mma, 128x128 tiles) ----------------
__global__ __launch_bounds__(256) void k_qkv(const float* __restrict__ x,
                                             float* __restrict__ Cdst) {
    __shared__ float As[2][16][136];
    __shared__ float Bs[2][16][136];

    const int t = threadIdx.x;
    const int b = blockIdx.z;
    const int m0 = blockIdx.y * 128;
    const int n0 = blockIdx.x * 128;

    const float* Ab = g_wt;
    const float* Bb = x + (size_t)b * CC * NN;
    float* Cb = Cdst + (size_t)b * THID * NN;

    const int id0 = t, id1 = t + 256;
    const int ar0 = id0 >> 5, ac0 = (id0 & 31) * 4;
    const int ar1 = id1 >> 5, ac1 = (id1 & 31) * 4;
    unsigned sA0[2], sA1[2], sB0[2], sB1[2];
#pragma unroll
    for (int s = 0; s < 2; s++) {
        sA0[s] = (unsigned)__cvta_generic_to_shared(&As[s][ar0][ac0]);
        sA1[s] = (unsigned)__cvta_generic_to_shared(&As[s][ar1][ac1]);
        sB0[s] = (unsigned)__cvta_generic_to_shared(&Bs[s][ar0][ac0]);
        sB1[s] = (unsigned)__cvta_generic_to_shared(&Bs[s][ar1][ac1]);
    }

    const int wid = t >> 5, lane = t & 31;
    const int wm = (wid >> 2) * 64;
    const int wn = (wid & 3) * 32;
    const int g = lane >> 2, t4 = lane & 3;

    float acc[4][4][4];
#pragma unroll
    for (int mt = 0; mt < 4; mt++)
#pragma unroll
        for (int nt = 0; nt < 4; nt++)
#pragma unroll
            for (int r = 0; r < 4; r++) acc[mt][nt][r] = 0.f;

    const int NK = CC / 16;
    CP16(sA0[0], Ab + (size_t)ar0 * THID + m0 + ac0);
    CP16(sA1[0], Ab + (size_t)ar1 * THID + m0 + ac1);
    CP16(sB0[0], Bb + (size_t)ar0 * NN + n0 + ac0);
    CP16(sB1[0], Bb + (size_t)ar1 * NN + n0 + ac1);
    CP_COMMIT();

    for (int kt = 0; kt < NK; kt++) {
        if (kt + 1 < NK) {
            const int k0 = (kt + 1) * 16;
            const int buf = (kt + 1) & 1;
            CP16(sA0[buf], Ab + (size_t)(k0 + ar0) * THID + m0 + ac0);
            CP16(sA1[buf], Ab + (size_t)(k0 + ar1) * THID + m0 + ac1);
            CP16(sB0[buf], Bb + (size_t)(k0 + ar0) * NN + n0 + ac0);
            CP16(sB1[buf], Bb + (size_t)(k0 + ar1) * NN + n0 + ac1);
            CP_COMMIT();
            CP_WAIT1();
        } else {
            CP_WAIT0();
        }
        __syncthreads();
        const int buf = kt & 1;
#pragma unroll
        for (int kk = 0; kk < 16; kk += 8) {
            uint32_t a[4][4], bf[4][2];
#pragma unroll
            for (int mt = 0; mt < 4; mt++) {
                int mr = wm + mt * 16 + g;
                a[mt][0] = f2tf32(As[buf][kk + t4][mr]);
                a[mt][1] = f2tf32(As[buf][kk + t4][mr + 8]);
                a[mt][2] = f2tf32(As[buf][kk + t4 + 4][mr]);
                a[mt][3] = f2tf32(As[buf][kk + t4 + 4][mr + 8]);
            }
#pragma unroll
            for (int nt = 0; nt < 4; nt++) {
                int nc = wn + nt * 8 + g;
                bf[nt][0] = f2tf32(Bs[buf][kk + t4][nc]);
                bf[nt][1] = f2tf32(Bs[buf][kk + t4 + 4][nc]);
            }
#pragma unroll
            for (int mt = 0; mt < 4; mt++)
#pragma unroll
                for (int nt = 0; nt < 4; nt++) mma_tf32(acc[mt][nt], a[mt], bf[nt]);
        }
        __syncthreads();
    }
#pragma unroll
    for (int mt = 0; mt < 4; mt++) {
        int row = m0 + wm + mt * 16 + g;
#pragma unroll
        for (int nt = 0; nt < 4; nt++) {
            int col = n0 + wn + nt * 8 + 2 * t4;
            *(float2*)(Cb + (size_t)row * NN + col) = make_float2(acc[mt][nt][0], acc[mt][nt][1]);
            *(float2*)(Cb + (size_t)(row + 8) * NN + col) = make_float2(acc[mt][nt][2], acc[mt][nt][3]);
        }
    }
}

// ---------------- K2: context partials via tf32 mma + fused exp-sum ----------------
// ctxp[d][e] += exp(k[d,n]) * v[e,n]  over this split's n-range; sump[d] += exp(k[d,n])
__global__ __launch_bounds__(128) void k_context() {
    __shared__ float Ks[64][36];
    __shared__ float Vs[64][36];
    int t = threadIdx.x;
    int sp = blockIdx.x, h = blockIdx.y, b = blockIdx.z;
    const float* kg = g_qkv + ((size_t)b * THID + HID + h * 64) * NN + sp * 512;
    const float* vg = g_qkv + ((size_t)b * THID + 2 * HID + h * 64) * NN + sp * 512;
    int wid = t >> 5, lane = t & 31;
    int g = lane >> 2, t4 = lane & 3;
    int wm = wid * 16;
    int lrow = t >> 3, lcol = (t & 7) * 4;    // per-thread load slot

    float acc[8][4];
#pragma unroll
    for (int nt = 0; nt < 8; nt++)
#pragma unroll
        for (int r = 0; r < 4; r++) acc[nt][r] = 0.f;
    float esum[4] = {0.f, 0.f, 0.f, 0.f};

    for (int c0 = 0; c0 < 512; c0 += 32) {
        __syncthreads();
#pragma unroll
        for (int i = 0; i < 4; i++) {
            int row = lrow + 16 * i;
            float4 kf = *(const float4*)(kg + (size_t)row * NN + c0 + lcol);
            float e0 = __expf(kf.x), e1 = __expf(kf.y), e2 = __expf(kf.z), e3 = __expf(kf.w);
            Ks[row][lcol] = e0; Ks[row][lcol + 1] = e1;
            Ks[row][lcol + 2] = e2; Ks[row][lcol + 3] = e3;
            esum[i] += e0 + e1 + e2 + e3;
            float4 vf = *(const float4*)(vg + (size_t)row * NN + c0 + lcol);
            *(float4*)&Vs[row][lcol] = vf;
        }
        __syncthreads();
#pragma unroll
        for (int kk = 0; kk < 32; kk += 8) {
            uint32_t a[4], bf[2];
            a[0] = f2tf32(Ks[wm + g][kk + t4]);
            a[1] = f2tf32(Ks[wm + 8 + g][kk + t4]);
            a[2] = f2tf32(Ks[wm + g][kk + t4 + 4]);
            a[3] = f2tf32(Ks[wm + 8 + g][kk + t4 + 4]);
#pragma unroll
            for (int nt = 0; nt < 8; nt++) {
                bf[0] = f2tf32(Vs[nt * 8 + g][kk + t4]);
                bf[1] = f2tf32(Vs[nt * 8 + g][kk + t4 + 4]);
                mma_tf32(acc[nt], a, bf);
            }
        }
    }
    // exp-sum partials: reduce across the 8 lanes sharing a row-group
#pragma unroll
    for (int i = 0; i < 4; i++) {
#pragma unroll
        for (int o = 1; o < 8; o <<= 1) esum[i] += __shfl_xor_sync(0xffffffffu, esum[i], o);
    }
    if ((lane & 7) == 0) {
        float* sp_out = g_sump + ((size_t)sp * BB + b) * HID + h * 64;
#pragma unroll
        for (int i = 0; i < 4; i++) sp_out[lrow + 16 * i] = esum[i];
    }
    float* op = g_ctxp + (((size_t)sp * BB + b) * HH + h) * (DD * DD);
#pragma unroll
    for (int nt = 0; nt < 8; nt++) {
        int col = nt * 8 + 2 * t4;
        *(float2*)(op + (wm + g) * DD + col) = make_float2(acc[nt][0], acc[nt][1]);
        *(float2*)(op + (wm + 8 + g) * DD + col) = make_float2(acc[nt][2], acc[nt][3]);
    }
}

// ---------------- K3: reduce partials, divide by exp-sum ----------------
__global__ __launch_bounds__(256) void k_ctxred() {
    int idx = blockIdx.x * 256 + threadIdx.x;
    float s = 0.f;
#pragma unroll
    for (int p = 0; p < NSPLIT; p++) s += g_ctxp[(size_t)p * (BB * HH * DD * DD) + idx];
    int d = (idx >> 6) & 63;
    int h = (idx >> 12) & 7;
    int b = idx >> 15;
    float den = 0.f;
#pragma unroll
    for (int p = 0; p < NSPLIT; p++) den += g_sump[((size_t)p * BB + b) * HID + h * 64 + d];
    g_ctx[idx] = s / den;
}

// ---------------- K4: A^T[b][hd][c] = sum_e wout[c][h64+e]*ctx[d][e] ----------------
__global__ __launch_bounds__(128) void k_Agemm(const float* __restrict__ wout) {
    __shared__ float Wouts[128][64];
    __shared__ float ctxs[64][64];
    int t = threadIdx.x;
    int cseg = blockIdx.x, h = blockIdx.y, b = blockIdx.z;
    int cbase = cseg * 128;
#pragma unroll
    for (int i = 0; i < 16; i++) {
        int lin4 = t + i * 128;
        int c = lin4 >> 4, e4 = lin4 & 15;
        *(float4*)&Wouts[c][e4 * 4] = *(const float4*)(wout + (size_t)(cbase + c) * HID + h * 64 + e4 * 4);
    }
    const float* ctxg = g_ctx + ((size_t)b * HH + h) * DD * DD;
#pragma unroll
    for (int i = 0; i < 8; i++) {
        int lin4 = t + i * 128;
        int d = lin4 >> 4, e4 = lin4 & 15;
        *(float4*)&ctxs[d][e4 * 4] = *(const float4*)(ctxg + d * 64 + e4 * 4);
    }
    __syncthreads();
    float acc[64];
#pragma unroll
    for (int d = 0; d < 64; d++) acc[d] = 0.f;
    for (int e = 0; e < 64; e++) {
        float w = Wouts[t][e];
#pragma unroll
        for (int d = 0; d < 64; d++) acc[d] = fmaf(w, ctxs[d][e], acc[d]);
    }
    float* op = g_At + ((size_t)b * HID + h * 64) * CC + cbase + t;
    for (int d = 0; d < 64; d++) op[(size_t)d * CC] = acc[d];
}

// ---------------- K5: fused q-softmax + output GEMM + bias + RMSNorm ----------------
// One block owns all 256 output rows for a 64-wide n-tile of one batch.
__global__ __launch_bounds__(256) void k_out(const float* __restrict__ bo,
                                             const float* __restrict__ gn,
                                             float* __restrict__ y) {
    __shared__ float Qs[64][72];
    __shared__ float As[16][264];
    __shared__ float redM[4][64];
    __shared__ float redS[4][64];
    __shared__ float colM[64];
    __shared__ float colS[64];
    __shared__ float sred[64][4];
    __shared__ float cscale[64];

    int t = threadIdx.x;
    int b = blockIdx.y, n0 = blockIdx.x * 64;
    int wid = t >> 5, lane = t & 31;
    int g = lane >> 2, t4 = lane & 3;
    int wm = (wid >> 1) * 64, wn = (wid & 1) * 32;
    int part = t >> 6, col = t & 63;

    float acc[4][4][4];
#pragma unroll
    for (int mt = 0; mt < 4; mt++)
#pragma unroll
        for (int nt = 0; nt < 4; nt++)
#pragma unroll
            for (int r = 0; r < 4; r++) acc[mt][nt][r] = 0.f;

    for (int h = 0; h < 8; h++) {
        __syncthreads();
        // load q tile [64 d][64 n]
#pragma unroll
        for (int i = 0; i < 4; i++) {
            int lin4 = t + i * 256;
            int row = lin4 >> 4, c4 = (lin4 & 15) * 4;
            *(float4*)&Qs[row][c4] =
                *(const float4*)(g_qkv + ((size_t)b * THID + h * 64 + row) * NN + n0 + c4);
        }
        __syncthreads();
        // softmax over d per column (4 threads per column)
        float lm = -1e30f;
#pragma unroll
        for (int r = 0; r < 16; r++) lm = fmaxf(lm, Qs[part * 16 + r][col]);
        redM[part][col] = lm;
        __syncthreads();
        float M = fmaxf(fmaxf(redM[0][col], redM[1][col]), fmaxf(redM[2][col], redM[3][col]));
        float ls = 0.f;
#pragma unroll
        for (int r = 0; r < 16; r++) ls += __expf(Qs[part * 16 + r][col] - M);
        redS[part][col] = ls;
        __syncthreads();
        if (t < 64) {
            colM[t] = M;
            colS[t] = SCALE / (redS[0][t] + redS[1][t] + redS[2][t] + redS[3][t]);
        }
        __syncthreads();
#pragma unroll
        for (int i = 0; i < 16; i++) {
            int lin = t + i * 256;
            int d = lin >> 6, n = lin & 63;
            Qs[d][n] = __expf(Qs[d][n] - colM[n]) * colS[n];
        }
        // acc += At[h-block] @ Qs  (K=64 in 4 chunks of 16)
        for (int dc = 0; dc < 4; dc++) {
            __syncthreads();
#pragma unroll
            for (int i = 0; i < 4; i++) {
                int lin4 = t + i * 256;
                int row = lin4 >> 6, c4 = (lin4 & 63) * 4;
                *(float4*)&As[row][c4] =
                    *(const float4*)(g_At + ((size_t)b * HID + h * 64 + dc * 16 + row) * CC + c4);
            }
            __syncthreads();
#pragma unroll
            for (int kk = 0; kk < 16; kk += 8) {
                uint32_t a[4][4], bf[4][2];
#pragma unroll
                for (int mt = 0; mt < 4; mt++) {
                    int mr = wm + mt * 16 + g;
                    a[mt][0] = f2tf32(As[kk + t4][mr]);
                    a[mt][1] = f2tf32(As[kk + t4][mr + 8]);
                    a[mt][2] = f2tf32(As[kk + t4 + 4][mr]);
                    a[mt][3] = f2tf32(As[kk + t4 + 4][mr + 8]);
                }
#pragma unroll
                for (int nt = 0; nt < 4; nt++) {
                    int nc = wn + nt * 8 + g;
                    bf[nt][0] = f2tf32(Qs[dc * 16 + kk + t4][nc]);
                    bf[nt][1] = f2tf32(Qs[dc * 16 + kk + t4 + 4][nc]);
                }
#pragma unroll
                for (int mt = 0; mt < 4; mt++)
#pragma unroll
                    for (int nt = 0; nt < 4; nt++) mma_tf32(acc[mt][nt], a[mt], bf[nt]);
            }
        }
    }
    // bias + ssq partials
    float ps[4][2];
#pragma unroll
    for (int nt = 0; nt < 4; nt++) { ps[nt][0] = 0.f; ps[nt][1] = 0.f; }
#pragma unroll
    for (int mt = 0; mt < 4; mt++) {
        int row = wm + mt * 16 + g;
        float b0v = bo[row], b1v = bo[row + 8];
#pragma unroll
        for (int nt = 0; nt < 4; nt++) {
            acc[mt][nt][0] += b0v;
            acc[mt][nt][1] += b0v;
            acc[mt][nt][2] += b1v;
            acc[mt][nt][3] += b1v;
            ps[nt][0] += acc[mt][nt][0] * acc[mt][nt][0] + acc[mt][nt][2] * acc[mt][nt][2];
            ps[nt][1] += acc[mt][nt][1] * acc[mt][nt][1] + acc[mt][nt][3] * acc[mt][nt][3];
        }
    }
#pragma unroll
    for (int nt = 0; nt < 4; nt++)
#pragma unroll
        for (int j = 0; j < 2; j++) {
#pragma unroll
            for (int o = 4; o <= 16; o <<= 1)
                ps[nt][j] += __shfl_xor_sync(0xffffffffu, ps[nt][j], o);
        }
    if (g == 0) {
#pragma unroll
        for (int nt = 0; nt < 4; nt++)
#pragma unroll
            for (int j = 0; j < 2; j++)
                sred[wn + nt * 8 + 2 * t4 + j][wid >> 1] = ps[nt][j];
    }
    __syncthreads();
    if (t < 64) {
        float tot = sred[t][0] + sred[t][1] + sred[t][2] + sred[t][3];
        cscale[t] = SQRTC / fmaxf(sqrtf(tot), 1e-12f);
    }
    __syncthreads();
#pragma unroll
    for (int mt = 0; mt < 4; mt++) {
        int row = wm + mt * 16 + g;
        float g0 = gn[row], g1 = gn[row + 8];
#pragma unroll
        for (int nt = 0; nt < 4; nt++) {
            int c = wn + nt * 8 + 2 * t4;
            float s0 = cscale[c], s1 = cscale[c + 1];
            *(float2*)(y + ((size_t)b * CC + row) * NN + n0 + c) =
                make_float2(acc[mt][nt][0] * s0 * g0, acc[mt][nt][1] * s1 * g0);
            *(float2*)(y + ((size_t)b * CC + row + 8) * NN + n0 + c) =
                make_float2(acc[mt][nt][2] * s0 * g1, acc[mt][nt][3] * s1 * g1);
        }
    }
}

// ---------------- launch ----------------
extern "C" void kernel_launch(void* const* d_in, const int* in_sizes, int n_in,
                              void* d_out, int out_size) {
    const float* x      = (const float*)d_in[0];
    const float* w_qkv  = (const float*)d_in[1];
    const float* w_out  = (const float*)d_in[2];
    const float* b_out  = (const float*)d_in[3];
    const float* g_norm = (const float*)d_in[4];
    float* y = (float*)d_out;

    float* qkv_ptr = nullptr;
    cudaGetSymbolAddress((void**)&qkv_ptr, g_qkv);

    k_wt<<<dim3(CC / 32, THID / 32), dim3(32, 8)>>>(w_qkv);
    k_qkv<<<dim3(NN / 128, THID / 128, BB), 256>>>(x, qkv_ptr);
    k_context<<<dim3(NSPLIT, HH, BB), 128>>>();
    k_ctxred<<<(BB * HH * DD * DD) / 256, 256>>>();
    k_Agemm<<<dim3(2, HH, BB), 128>>>(w_out);
    k_out<<<dim3(NN / 64, BB), 256>>>(b_out, g_norm, y);
}